// round 1
// baseline (speedup 1.0000x reference)
#include <cuda_runtime.h>
#include <cuda_bf16.h>
#include <math.h>

// Problem constants (fixed by reference):
//   SIGMA=8 -> 1/(2*sigma^2) = 1/128
//   C_SIZE=512, STRIDE=8 -> C = 64 grid cells per axis, cood[k] = 8k+4
//   B=16, N=512 points, BG_RATIO=0.15, EPS=1e-5
//   out[b, p, i*64+j], p in [0,512], fp32, shape [B, 513, 4096]

#define CGRID   64
#define NPTS    512
#define PCHUNK  128
#define NCHUNK  (NPTS / PCHUNK)
#define TILE_I  4
#define NTHREADS 256

__global__ __launch_bounds__(NTHREADS)
void post_prob_kernel(const float* __restrict__ points,
                      const float* __restrict__ st_sizes,
                      float* __restrict__ out)
{
    const int b  = blockIdx.y;
    const int i0 = blockIdx.x * TILE_I;
    const int tid = threadIdx.x;
    const int ti = tid >> 6;        // 0..3   (row within tile)
    const int j  = tid & 63;        // 0..63  (x cell)
    const int i  = i0 + ti;         // y cell

    const float ci = (float)(i * 8 + 4);
    const float cj = (float)(j * 8 + 4);
    const float kInv = 1.0f / 128.0f;   // 1/(2*sigma^2), exact

    const float2* __restrict__ ptb = (const float2*)(points) + (size_t)b * NPTS;

    __shared__ float2 pts_s[PCHUNK];                // 1 KB
    __shared__ float  Ex_s[PCHUNK * CGRID];         // 32 KB, [p][j]
    __shared__ float  Ey_s[TILE_I * PCHUNK];        // 2 KB,  [ti][p]

    float mind = 3.4e38f;
    float sum  = 0.0f;

    // ---------------- Phase A: accumulate sum of exp, min distance ----------
    for (int c = 0; c < NCHUNK; ++c) {
        __syncthreads();
        if (tid < PCHUNK) pts_s[tid] = ptb[c * PCHUNK + tid];
        __syncthreads();

        // Ex_s[p][jj] = exp(-(x_p - cood_jj)^2 / 128):  8192 entries
        #pragma unroll
        for (int k = 0; k < (PCHUNK * CGRID) / NTHREADS; ++k) {
            int idx = tid + k * NTHREADS;
            int p  = idx >> 6;
            int jj = idx & 63;
            float dx = pts_s[p].x - (float)(jj * 8 + 4);
            Ex_s[idx] = __expf(-dx * dx * kInv);
        }
        // Ey_s[ii][p]: 512 entries
        #pragma unroll
        for (int k = 0; k < (TILE_I * PCHUNK) / NTHREADS; ++k) {
            int idx = tid + k * NTHREADS;
            int ii = idx >> 7;          // idx / PCHUNK
            int p  = idx & (PCHUNK - 1);
            float dy = pts_s[p].y - (float)((i0 + ii) * 8 + 4);
            Ey_s[idx] = __expf(-dy * dy * kInv);
        }
        __syncthreads();

        #pragma unroll 8
        for (int p = 0; p < PCHUNK; ++p) {
            float2 pt = pts_s[p];
            float dy = pt.y - ci;
            float dx = pt.x - cj;
            float d  = fmaf(dx, dx, dy * dy);
            mind = fminf(mind, d);
            sum += Ey_s[ti * PCHUNK + p] * Ex_s[p * CGRID + j];
        }
    }

    // ---------------- Background term + normalization -----------------------
    float s = st_sizes[b] * 0.15f;
    s = s * s;
    float bg_dis = s / (mind + 1e-5f);
    float ebg = __expf(-bg_dis * kInv);
    float invt = 1.0f / (sum + ebg);

    const size_t M = (size_t)CGRID * CGRID;          // 4096
    const size_t obase = (size_t)b * (NPTS + 1) * M + (size_t)i * CGRID + j;
    out[obase + (size_t)NPTS * M] = ebg * invt;       // background plane p=512

    // ---------------- Phase B: normalized writes ----------------------------
    for (int c = 0; c < NCHUNK; ++c) {
        __syncthreads();
        if (tid < PCHUNK) pts_s[tid] = ptb[c * PCHUNK + tid];
        __syncthreads();

        #pragma unroll
        for (int k = 0; k < (PCHUNK * CGRID) / NTHREADS; ++k) {
            int idx = tid + k * NTHREADS;
            int p  = idx >> 6;
            int jj = idx & 63;
            float dx = pts_s[p].x - (float)(jj * 8 + 4);
            Ex_s[idx] = __expf(-dx * dx * kInv);
        }
        #pragma unroll
        for (int k = 0; k < (TILE_I * PCHUNK) / NTHREADS; ++k) {
            int idx = tid + k * NTHREADS;
            int ii = idx >> 7;
            int p  = idx & (PCHUNK - 1);
            float dy = pts_s[p].y - (float)((i0 + ii) * 8 + 4);
            Ey_s[idx] = __expf(-dy * dy * kInv);
        }
        __syncthreads();

        float* __restrict__ op = out + obase + (size_t)c * PCHUNK * M;
        #pragma unroll 4
        for (int p = 0; p < PCHUNK; ++p) {
            op[(size_t)p * M] = (Ey_s[ti * PCHUNK + p] * Ex_s[p * CGRID + j]) * invt;
        }
    }
}

extern "C" void kernel_launch(void* const* d_in, const int* in_sizes, int n_in,
                              void* d_out, int out_size)
{
    const float* points   = (const float*)d_in[0];   // [B, 512, 2] fp32
    const float* st_sizes = (const float*)d_in[1];   // [B] fp32
    float* out = (float*)d_out;                      // [B, 513, 4096] fp32

    const int B = in_sizes[1];                       // 16

    dim3 grid(CGRID / TILE_I, B);                    // (16, 16) = 256 blocks
    dim3 block(NTHREADS);
    post_prob_kernel<<<grid, block>>>(points, st_sizes, out);
}

// round 2
// speedup vs baseline: 1.0990x; 1.0990x over previous
#include <cuda_runtime.h>
#include <cuda_bf16.h>

// Problem constants (fixed):
//   SIGMA=8 -> 1/(2*sigma^2) = 1/128, C_SIZE=512, STRIDE=8 -> 64x64 grid,
//   cood[k]=8k+4, B=16, N=512, BG_RATIO=0.15, EPS=1e-5
//   out[b, p, i*64+j], p in [0,512], fp32, [16, 513, 4096]

#define CGRID   64
#define NPTS    512
#define PCHUNK  64
#define NCHUNK  (NPTS / PCHUNK)     // 8
#define BFIX    16
#define MPIX    (CGRID * CGRID)     // 4096
#define KINV    (1.0f / 128.0f)

// Scratch (no runtime allocation allowed)
__device__ float g_psum[BFIX * NCHUNK * MPIX];   // per-chunk partial sums
__device__ float g_pmin[BFIX * NCHUNK * MPIX];   // per-chunk partial mins
__device__ float g_invt[BFIX * MPIX];            // 1/denominator per pixel

// ---------------------------------------------------------------------------
// K1a: per (b, chunk, 16-row tile): partial exp-sum + partial min distance.
// Thread layout: ti = tid>>4 (16 rows), jg = tid&15 (4 j-cells each).
// ---------------------------------------------------------------------------
__global__ __launch_bounds__(256)
void k_partial(const float* __restrict__ points)
{
    const int b   = blockIdx.z;
    const int c   = blockIdx.y;
    const int i0  = blockIdx.x * 16;
    const int tid = threadIdx.x;
    const int ti  = tid >> 4;
    const int jg  = tid & 15;
    const int i   = i0 + ti;

    __shared__ float2 pts_s[PCHUNK];            // 0.5 KB
    __shared__ float  Ex_s[PCHUNK * CGRID];     // 16 KB  [p][j]
    __shared__ float  Ey_s[16 * PCHUNK];        // 4 KB   [ti][p]

    const float2* ptb = (const float2*)points + b * NPTS + c * PCHUNK;
    if (tid < PCHUNK) pts_s[tid] = ptb[tid];
    __syncthreads();

    #pragma unroll
    for (int k = 0; k < (PCHUNK * CGRID) / 256; ++k) {
        int idx = tid + k * 256;
        int p = idx >> 6, jj = idx & 63;
        float dx = pts_s[p].x - (float)(jj * 8 + 4);
        Ex_s[idx] = __expf(-dx * dx * KINV);
    }
    #pragma unroll
    for (int k = 0; k < (16 * PCHUNK) / 256; ++k) {
        int idx = tid + k * 256;
        int ii = idx >> 6, p = idx & (PCHUNK - 1);
        float dy = pts_s[p].y - (float)((i0 + ii) * 8 + 4);
        Ey_s[idx] = __expf(-dy * dy * KINV);
    }
    __syncthreads();

    const float ci  = (float)(i * 8 + 4);
    const float cj0 = (float)(jg * 32 + 4);   // j = jg*4 + {0..3}, cood = j*8+4
    float4 sum  = make_float4(0.f, 0.f, 0.f, 0.f);
    float4 mind = make_float4(1e30f, 1e30f, 1e30f, 1e30f);
    const float4* Ex4 = (const float4*)Ex_s;

    #pragma unroll 4
    for (int p = 0; p < PCHUNK; ++p) {
        float2 pt = pts_s[p];
        float  ey = Ey_s[ti * PCHUNK + p];
        float4 ex = Ex4[p * 16 + jg];
        float dy  = pt.y - ci;
        float dy2 = dy * dy;
        float dx0 = pt.x - cj0;
        float dx1 = pt.x - (cj0 + 8.f);
        float dx2 = pt.x - (cj0 + 16.f);
        float dx3 = pt.x - (cj0 + 24.f);
        float d0 = fmaf(dx0, dx0, dy2);
        float d1 = fmaf(dx1, dx1, dy2);
        float d2 = fmaf(dx2, dx2, dy2);
        float d3 = fmaf(dx3, dx3, dy2);
        mind.x = fminf(mind.x, d0);
        mind.y = fminf(mind.y, d1);
        mind.z = fminf(mind.z, d2);
        mind.w = fminf(mind.w, d3);
        sum.x = fmaf(ey, ex.x, sum.x);
        sum.y = fmaf(ey, ex.y, sum.y);
        sum.z = fmaf(ey, ex.z, sum.z);
        sum.w = fmaf(ey, ex.w, sum.w);
    }

    int o = (b * NCHUNK + c) * MPIX + i * CGRID + jg * 4;
    *(float4*)(g_psum + o) = sum;
    *(float4*)(g_pmin + o) = mind;
}

// ---------------------------------------------------------------------------
// K1b: reduce chunk partials -> invt per pixel; write background plane p=512.
// ---------------------------------------------------------------------------
__global__ __launch_bounds__(256)
void k_combine(const float* __restrict__ st_sizes, float* __restrict__ out)
{
    int idx = blockIdx.x * 256 + threadIdx.x;      // over BFIX*MPIX/4 = 16384
    int b = idx >> 10;                              // MPIX/4 = 1024
    int r = idx & 1023;

    const float4* ps = (const float4*)g_psum;
    const float4* pm = (const float4*)g_pmin;
    int base = b * NCHUNK * 1024 + r;

    float4 sum = make_float4(0.f, 0.f, 0.f, 0.f);
    float4 mn  = make_float4(1e30f, 1e30f, 1e30f, 1e30f);
    #pragma unroll
    for (int c = 0; c < NCHUNK; ++c) {
        float4 s = ps[base + c * 1024];
        float4 m = pm[base + c * 1024];
        sum.x += s.x; sum.y += s.y; sum.z += s.z; sum.w += s.w;
        mn.x = fminf(mn.x, m.x); mn.y = fminf(mn.y, m.y);
        mn.z = fminf(mn.z, m.z); mn.w = fminf(mn.w, m.w);
    }

    float sc = st_sizes[b] * 0.15f;
    float ss = sc * sc;
    float4 invt, bgp;
    {
        float ebg = __expf(-(ss / (mn.x + 1e-5f)) * KINV);
        float iv = 1.0f / (sum.x + ebg); invt.x = iv; bgp.x = ebg * iv;
    }
    {
        float ebg = __expf(-(ss / (mn.y + 1e-5f)) * KINV);
        float iv = 1.0f / (sum.y + ebg); invt.y = iv; bgp.y = ebg * iv;
    }
    {
        float ebg = __expf(-(ss / (mn.z + 1e-5f)) * KINV);
        float iv = 1.0f / (sum.z + ebg); invt.z = iv; bgp.z = ebg * iv;
    }
    {
        float ebg = __expf(-(ss / (mn.w + 1e-5f)) * KINV);
        float iv = 1.0f / (sum.w + ebg); invt.w = iv; bgp.w = ebg * iv;
    }

    ((float4*)g_invt)[b * 1024 + r] = invt;
    ((float4*)out)[(b * 513 + 512) * 1024 + r] = bgp;   // background plane
}

// ---------------------------------------------------------------------------
// K2: normalized writes for point planes (pure-bandwidth phase).
// ---------------------------------------------------------------------------
__global__ __launch_bounds__(256)
void k_write(const float* __restrict__ points, float* __restrict__ out)
{
    const int b   = blockIdx.z;
    const int c   = blockIdx.y;
    const int i0  = blockIdx.x * 16;
    const int tid = threadIdx.x;
    const int ti  = tid >> 4;
    const int jg  = tid & 15;
    const int i   = i0 + ti;

    __shared__ float2 pts_s[PCHUNK];
    __shared__ float  Ex_s[PCHUNK * CGRID];
    __shared__ float  Ey_s[16 * PCHUNK];

    const float2* ptb = (const float2*)points + b * NPTS + c * PCHUNK;
    if (tid < PCHUNK) pts_s[tid] = ptb[tid];
    __syncthreads();

    #pragma unroll
    for (int k = 0; k < (PCHUNK * CGRID) / 256; ++k) {
        int idx = tid + k * 256;
        int p = idx >> 6, jj = idx & 63;
        float dx = pts_s[p].x - (float)(jj * 8 + 4);
        Ex_s[idx] = __expf(-dx * dx * KINV);
    }
    #pragma unroll
    for (int k = 0; k < (16 * PCHUNK) / 256; ++k) {
        int idx = tid + k * 256;
        int ii = idx >> 6, p = idx & (PCHUNK - 1);
        float dy = pts_s[p].y - (float)((i0 + ii) * 8 + 4);
        Ey_s[idx] = __expf(-dy * dy * KINV);
    }
    __syncthreads();

    float4 invt = ((const float4*)g_invt)[b * 1024 + i * 16 + jg];
    float* op = out + ((size_t)b * 513 + c * PCHUNK) * MPIX + i * CGRID + jg * 4;
    const float4* Ex4 = (const float4*)Ex_s;

    #pragma unroll 4
    for (int p = 0; p < PCHUNK; ++p) {
        float  ey = Ey_s[ti * PCHUNK + p];
        float4 ex = Ex4[p * 16 + jg];
        float4 v;
        v.x = (ey * ex.x) * invt.x;
        v.y = (ey * ex.y) * invt.y;
        v.z = (ey * ex.z) * invt.z;
        v.w = (ey * ex.w) * invt.w;
        *(float4*)(op + (size_t)p * MPIX) = v;
    }
}

// ---------------------------------------------------------------------------
extern "C" void kernel_launch(void* const* d_in, const int* in_sizes, int n_in,
                              void* d_out, int out_size)
{
    const float* points   = (const float*)d_in[0];   // [16, 512, 2]
    const float* st_sizes = (const float*)d_in[1];   // [16]
    float* out = (float*)d_out;                      // [16, 513, 4096]

    dim3 g1(CGRID / 16, NCHUNK, BFIX);               // (4, 8, 16) = 512 blocks
    k_partial<<<g1, 256>>>(points);
    k_combine<<<(BFIX * MPIX / 4) / 256, 256>>>(st_sizes, out);
    k_write<<<g1, 256>>>(points, out);
}

// round 3
// speedup vs baseline: 1.1913x; 1.0840x over previous
#include <cuda_runtime.h>
#include <cuda_bf16.h>

// Fixed problem constants:
//   SIGMA=8 -> 1/(2*sigma^2)=1/128, C_SIZE=512, STRIDE=8 -> 64x64 grid,
//   cood[k]=8k+4, B=16, N=512, BG_RATIO=0.15, EPS=1e-5
//   out[b, p, i*64+j], p in [0,512], fp32, [16, 513, 4096]

#define CGRID   64
#define NPTS    512
#define PCHUNK  32
#define NCHUNK  (NPTS / PCHUNK)     // 16
#define BFIX    16
#define MPIX    (CGRID * CGRID)     // 4096
#define KINV    (1.0f / 128.0f)

// Scratch (static; no runtime allocation allowed)
__device__ float g_psum[BFIX * NCHUNK * MPIX];   // per-chunk partial exp-sums (4 MB)
__device__ float g_pmax[BFIX * NCHUNK * MPIX];   // per-chunk max products    (4 MB)
__device__ float g_invt[BFIX * MPIX];            // 1/denominator per pixel

// ---------------------------------------------------------------------------
// K1a: per (b, chunk, 16-row tile): partial exp-sum + max product.
//      exp(-((y-ci)^2+(x-cj)^2)/128) = Ey[p,i]*Ex[p,j]  (separable)
//      min-distance recovered later as -128*ln(max product).
// ---------------------------------------------------------------------------
__global__ __launch_bounds__(256)
void k_partial(const float* __restrict__ points)
{
    const int b   = blockIdx.z;
    const int c   = blockIdx.y;
    const int i0  = blockIdx.x * 16;
    const int tid = threadIdx.x;
    const int ti  = tid >> 4;      // 0..15 row in tile
    const int jg  = tid & 15;      // 0..15, owns j = jg*4 + {0..3}

    __shared__ float2 pts_s[PCHUNK];            // 256 B
    __shared__ float  Ex_s[PCHUNK * CGRID];     // 8 KB  [p][j]
    __shared__ float  Ey_s[16 * PCHUNK];        // 2 KB  [ti][p]

    const float2* ptb = (const float2*)points + b * NPTS + c * PCHUNK;
    if (tid < PCHUNK) pts_s[tid] = ptb[tid];
    __syncthreads();

    #pragma unroll
    for (int k = 0; k < (PCHUNK * CGRID) / 256; ++k) {   // 8 iters
        int idx = tid + k * 256;
        int p = idx >> 6, jj = idx & 63;
        float dx = pts_s[p].x - (float)(jj * 8 + 4);
        Ex_s[idx] = __expf(-dx * dx * KINV);
    }
    #pragma unroll
    for (int k = 0; k < (16 * PCHUNK) / 256; ++k) {      // 2 iters
        int idx = tid + k * 256;
        int ii = idx >> 5, p = idx & (PCHUNK - 1);
        float dy = pts_s[p].y - (float)((i0 + ii) * 8 + 4);
        Ey_s[idx] = __expf(-dy * dy * KINV);
    }
    __syncthreads();

    float4 sum  = make_float4(0.f, 0.f, 0.f, 0.f);
    float4 mx   = make_float4(0.f, 0.f, 0.f, 0.f);
    const float4* Ex4 = (const float4*)Ex_s;

    #pragma unroll 8
    for (int p = 0; p < PCHUNK; ++p) {
        float  ey = Ey_s[ti * PCHUNK + p];
        float4 ex = Ex4[p * 16 + jg];
        float p0 = ey * ex.x;
        float p1 = ey * ex.y;
        float p2 = ey * ex.z;
        float p3 = ey * ex.w;
        sum.x += p0; sum.y += p1; sum.z += p2; sum.w += p3;
        mx.x = fmaxf(mx.x, p0); mx.y = fmaxf(mx.y, p1);
        mx.z = fmaxf(mx.z, p2); mx.w = fmaxf(mx.w, p3);
    }

    int o = (b * NCHUNK + c) * MPIX + (i0 + ti) * CGRID + jg * 4;
    *(float4*)(g_psum + o) = sum;
    *(float4*)(g_pmax + o) = mx;
}

// ---------------------------------------------------------------------------
// K1b: reduce chunk partials -> invt per pixel; write background plane p=512.
// ---------------------------------------------------------------------------
__global__ __launch_bounds__(256)
void k_combine(const float* __restrict__ st_sizes, float* __restrict__ out)
{
    int idx = blockIdx.x * 256 + threadIdx.x;      // over BFIX*MPIX/4 = 16384
    int b = idx >> 10;                              // MPIX/4 = 1024
    int r = idx & 1023;

    const float4* ps = (const float4*)g_psum;
    const float4* pm = (const float4*)g_pmax;
    int base = b * NCHUNK * 1024 + r;

    float4 sum = make_float4(0.f, 0.f, 0.f, 0.f);
    float4 mx  = make_float4(0.f, 0.f, 0.f, 0.f);
    #pragma unroll
    for (int c = 0; c < NCHUNK; ++c) {
        float4 s = ps[base + c * 1024];
        float4 m = pm[base + c * 1024];
        sum.x += s.x; sum.y += s.y; sum.z += s.z; sum.w += s.w;
        mx.x = fmaxf(mx.x, m.x); mx.y = fmaxf(mx.y, m.y);
        mx.z = fmaxf(mx.z, m.z); mx.w = fmaxf(mx.w, m.w);
    }

    float sc = st_sizes[b] * 0.15f;
    float ss = sc * sc;
    float4 invt, bgp;
    {
        float mind = -128.0f * __logf(fmaxf(mx.x, 1e-38f));
        float ebg = __expf(-(ss / (mind + 1e-5f)) * KINV);
        float iv = 1.0f / (sum.x + ebg); invt.x = iv; bgp.x = ebg * iv;
    }
    {
        float mind = -128.0f * __logf(fmaxf(mx.y, 1e-38f));
        float ebg = __expf(-(ss / (mind + 1e-5f)) * KINV);
        float iv = 1.0f / (sum.y + ebg); invt.y = iv; bgp.y = ebg * iv;
    }
    {
        float mind = -128.0f * __logf(fmaxf(mx.z, 1e-38f));
        float ebg = __expf(-(ss / (mind + 1e-5f)) * KINV);
        float iv = 1.0f / (sum.z + ebg); invt.z = iv; bgp.z = ebg * iv;
    }
    {
        float mind = -128.0f * __logf(fmaxf(mx.w, 1e-38f));
        float ebg = __expf(-(ss / (mind + 1e-5f)) * KINV);
        float iv = 1.0f / (sum.w + ebg); invt.w = iv; bgp.w = ebg * iv;
    }

    ((float4*)g_invt)[b * 1024 + r] = invt;
    ((float4*)out)[(b * 513 + 512) * 1024 + r] = bgp;   // background plane
}

// ---------------------------------------------------------------------------
// K2: normalized writes for the 512 point planes (bandwidth phase).
// ---------------------------------------------------------------------------
__global__ __launch_bounds__(256)
void k_write(const float* __restrict__ points, float* __restrict__ out)
{
    const int b   = blockIdx.z;
    const int c   = blockIdx.y;
    const int i0  = blockIdx.x * 16;
    const int tid = threadIdx.x;
    const int ti  = tid >> 4;
    const int jg  = tid & 15;
    const int i   = i0 + ti;

    __shared__ float2 pts_s[PCHUNK];
    __shared__ float  Ex_s[PCHUNK * CGRID];
    __shared__ float  Ey_s[16 * PCHUNK];

    const float2* ptb = (const float2*)points + b * NPTS + c * PCHUNK;
    if (tid < PCHUNK) pts_s[tid] = ptb[tid];
    __syncthreads();

    #pragma unroll
    for (int k = 0; k < (PCHUNK * CGRID) / 256; ++k) {
        int idx = tid + k * 256;
        int p = idx >> 6, jj = idx & 63;
        float dx = pts_s[p].x - (float)(jj * 8 + 4);
        Ex_s[idx] = __expf(-dx * dx * KINV);
    }
    #pragma unroll
    for (int k = 0; k < (16 * PCHUNK) / 256; ++k) {
        int idx = tid + k * 256;
        int ii = idx >> 5, p = idx & (PCHUNK - 1);
        float dy = pts_s[p].y - (float)((i0 + ii) * 8 + 4);
        Ey_s[idx] = __expf(-dy * dy * KINV);
    }
    __syncthreads();

    float4 invt = ((const float4*)g_invt)[b * 1024 + i * 16 + jg];
    float* op = out + ((size_t)b * 513 + c * PCHUNK) * MPIX + i * CGRID + jg * 4;
    const float4* Ex4 = (const float4*)Ex_s;

    #pragma unroll 8
    for (int p = 0; p < PCHUNK; ++p) {
        float  ey = Ey_s[ti * PCHUNK + p];
        float4 ex = Ex4[p * 16 + jg];
        float4 v;
        v.x = (ey * ex.x) * invt.x;
        v.y = (ey * ex.y) * invt.y;
        v.z = (ey * ex.z) * invt.z;
        v.w = (ey * ex.w) * invt.w;
        *(float4*)(op + (size_t)p * MPIX) = v;
    }
}

// ---------------------------------------------------------------------------
extern "C" void kernel_launch(void* const* d_in, const int* in_sizes, int n_in,
                              void* d_out, int out_size)
{
    const float* points   = (const float*)d_in[0];   // [16, 512, 2]
    const float* st_sizes = (const float*)d_in[1];   // [16]
    float* out = (float*)d_out;                      // [16, 513, 4096]

    dim3 g1(CGRID / 16, NCHUNK, BFIX);               // (4, 16, 16) = 1024 blocks
    k_partial<<<g1, 256>>>(points);
    k_combine<<<(BFIX * MPIX / 4) / 256, 256>>>(st_sizes, out);
    k_write<<<g1, 256>>>(points, out);
}